// round 1
// baseline (speedup 1.0000x reference)
#include <cuda_runtime.h>
#include <cuda_bf16.h>
#include <cstdint>

#define N_NODES_MAX 50000
#define NODE_DIM    128
#define HIDDEN      256
#define NCOLS       1024   // 4 segments of 256

// Scratch (static device globals — no runtime allocation)
__device__ float g_table[(size_t)N_NODES_MAX * NCOLS];   // ~204.8 MB
__device__ float g_Wbig[NODE_DIM * NCOLS];               // 512 KB
__device__ float g_c[HIDDEN];
__device__ int   g_is64;

// ---------------------------------------------------------------------------
// Detect whether edge_index is int64 (odd int32 words of nonneg int64 are 0)
// Deterministic, single thread, no state carried across replays.
// ---------------------------------------------------------------------------
__global__ void detect_kernel(const int* __restrict__ idx32) {
    int acc = 0;
    #pragma unroll 8
    for (int i = 1; i < 2048; i += 2) acc |= idx32[i];
    g_is64 = (acc == 0) ? 1 : 0;
}

// ---------------------------------------------------------------------------
// Build folded weights: Wbig[k][n], n = seg*256 + h
//   seg0: W1[k][h]*s[h]            (top, mlp1)
//   seg1: W1[128+k][h]*s[h]        (bot, mlp1)
//   seg2: W1[k+16][h]*s[h]         (top, rolled)
//   seg3: W1[(k+144)%256][h]*s[h]  (bot, rolled)
// and c[h] = b1[h]*s[h] + beta[h] - mean[h]*s[h]
// ---------------------------------------------------------------------------
__global__ void prep_kernel(const float* __restrict__ W1, const float* __restrict__ b1,
                            const float* __restrict__ gamma, const float* __restrict__ beta,
                            const float* __restrict__ mean, const float* __restrict__ var) {
    int i = blockIdx.x * blockDim.x + threadIdx.x;
    if (i < NODE_DIM * NCOLS) {
        int k = i >> 10;
        int n = i & 1023;
        int h = n & 255;
        int seg = n >> 8;
        int srcRow;
        if (seg == 0)      srcRow = k;
        else if (seg == 1) srcRow = 128 + k;
        else if (seg == 2) srcRow = k + 16;            // <= 143, no wrap
        else               srcRow = (k + 144) & 255;
        float s = gamma[h] * rsqrtf(var[h] + 1e-5f);
        g_Wbig[i] = W1[srcRow * 256 + h] * s;
    }
    if (i < HIDDEN) {
        float s = gamma[i] * rsqrtf(var[i] + 1e-5f);
        g_c[i] = b1[i] * s + beta[i] - mean[i] * s;
    }
}

// ---------------------------------------------------------------------------
// Tiled fp32 GEMM: g_table[M x 1024] = X[M x 128] @ g_Wbig[128 x 1024]
// BM=BN=128, BK=16, 256 threads, 8x8 per thread.
// ---------------------------------------------------------------------------
#define BM 128
#define BN 128
#define BK 16

__global__ __launch_bounds__(256) void gemm_kernel(const float* __restrict__ X, int M) {
    __shared__ float Xs[BK][BM];   // transposed: [k][m]
    __shared__ float Ws[BK][BN];

    int bm = blockIdx.y * BM;
    int bn = blockIdx.x * BN;
    int tid = threadIdx.x;
    int tx = tid & 15;   // col group (8 cols each)
    int ty = tid >> 4;   // row group (8 rows each)

    float acc[8][8];
    #pragma unroll
    for (int i = 0; i < 8; i++)
        #pragma unroll
        for (int j = 0; j < 8; j++) acc[i][j] = 0.f;

    for (int k0 = 0; k0 < NODE_DIM; k0 += BK) {
        // Load X tile (128 rows x 16 k) transposed. 512 float4 slots, 2/thread.
        #pragma unroll
        for (int q = 0; q < 2; q++) {
            int s = tid * 2 + q;
            int r  = s >> 2;        // row in tile
            int c4 = s & 3;         // k-quad
            int gr = bm + r;
            float4 v = make_float4(0.f, 0.f, 0.f, 0.f);
            if (gr < M) v = *(const float4*)(X + (size_t)gr * NODE_DIM + k0 + c4 * 4);
            Xs[c4 * 4 + 0][r] = v.x;
            Xs[c4 * 4 + 1][r] = v.y;
            Xs[c4 * 4 + 2][r] = v.z;
            Xs[c4 * 4 + 3][r] = v.w;
        }
        // Load W tile (16 k x 128 cols). 512 float4 slots, 2/thread.
        #pragma unroll
        for (int q = 0; q < 2; q++) {
            int s = tid * 2 + q;
            int r  = s >> 5;
            int c4 = s & 31;
            *(float4*)&Ws[r][c4 * 4] =
                *(const float4*)(g_Wbig + (size_t)(k0 + r) * NCOLS + bn + c4 * 4);
        }
        __syncthreads();

        #pragma unroll
        for (int k = 0; k < BK; k++) {
            float a[8], b[8];
            *(float4*)(a)     = *(float4*)&Xs[k][ty * 8];
            *(float4*)(a + 4) = *(float4*)&Xs[k][ty * 8 + 4];
            *(float4*)(b)     = *(float4*)&Ws[k][tx * 8];
            *(float4*)(b + 4) = *(float4*)&Ws[k][tx * 8 + 4];
            #pragma unroll
            for (int i = 0; i < 8; i++)
                #pragma unroll
                for (int j = 0; j < 8; j++)
                    acc[i][j] = fmaf(a[i], b[j], acc[i][j]);
        }
        __syncthreads();
    }

    #pragma unroll
    for (int i = 0; i < 8; i++) {
        int gr = bm + ty * 8 + i;
        if (gr >= M) continue;
        float* dst = g_table + (size_t)gr * NCOLS + bn + tx * 8;
        *(float4*)(dst)     = *(float4*)&acc[i][0];
        *(float4*)(dst + 4) = *(float4*)&acc[i][4];
    }
}

// ---------------------------------------------------------------------------
// Edge kernel: warp per edge.
// p1+p2 = sum_h relu(T[row][h]+T[col][256+h]+c[h])*W2[h]
//       + sum_h relu(T[row][512+h]+T[col][768+h]+c[h])*W2[h] + 2*b2
// out = sigmoid((p1+p2)/2)
// ---------------------------------------------------------------------------
__global__ __launch_bounds__(256) void edge_kernel(const void* __restrict__ idx,
                                                   const float* __restrict__ W2,
                                                   const float* __restrict__ b2,
                                                   float* __restrict__ out, int E) {
    int e = blockIdx.x * 8 + (threadIdx.x >> 5);
    if (e >= E) return;
    int lane = threadIdx.x & 31;

    int row, col;
    if (g_is64) {
        const long long* p = (const long long*)idx;
        row = (int)p[e];
        col = (int)p[E + e];
    } else {
        const int* p = (const int*)idx;
        row = p[e];
        col = p[E + e];
    }

    const float* Tr = g_table + (size_t)row * NCOLS;
    const float* Tc = g_table + (size_t)col * NCOLS;

    float acc = 0.f;
    #pragma unroll
    for (int part = 0; part < 2; part++) {
        int off = part * 128 + lane * 4;
        float4 a1 = *(const float4*)(Tr + off);
        float4 b1v = *(const float4*)(Tc + 256 + off);
        float4 a2 = *(const float4*)(Tr + 512 + off);
        float4 b2v = *(const float4*)(Tc + 768 + off);
        float4 cc = *(const float4*)(g_c + off);
        float4 w  = *(const float4*)(W2 + off);
        acc += fmaxf(a1.x + b1v.x + cc.x, 0.f) * w.x;
        acc += fmaxf(a1.y + b1v.y + cc.y, 0.f) * w.y;
        acc += fmaxf(a1.z + b1v.z + cc.z, 0.f) * w.z;
        acc += fmaxf(a1.w + b1v.w + cc.w, 0.f) * w.w;
        acc += fmaxf(a2.x + b2v.x + cc.x, 0.f) * w.x;
        acc += fmaxf(a2.y + b2v.y + cc.y, 0.f) * w.y;
        acc += fmaxf(a2.z + b2v.z + cc.z, 0.f) * w.z;
        acc += fmaxf(a2.w + b2v.w + cc.w, 0.f) * w.w;
    }
    #pragma unroll
    for (int s = 16; s; s >>= 1) acc += __shfl_xor_sync(0xFFFFFFFFu, acc, s);

    if (lane == 0) {
        float x = acc * 0.5f + b2[0];
        out[e] = 1.f / (1.f + expf(-x));
    }
}

// ---------------------------------------------------------------------------
extern "C" void kernel_launch(void* const* d_in, const int* in_sizes, int n_in,
                              void* d_out, int out_size) {
    const float* node_feat = (const float*)d_in[0];
    const void*  eidx      = d_in[1];
    const float* W1        = (const float*)d_in[2];
    const float* b1        = (const float*)d_in[3];
    const float* gamma     = (const float*)d_in[4];
    const float* beta      = (const float*)d_in[5];
    const float* mean      = (const float*)d_in[6];
    const float* var       = (const float*)d_in[7];
    const float* W2        = (const float*)d_in[8];
    const float* b2        = (const float*)d_in[9];
    float* out = (float*)d_out;

    int M = in_sizes[0] / NODE_DIM;   // 50000
    int E = out_size;                 // 300000

    detect_kernel<<<1, 1>>>((const int*)eidx);
    prep_kernel<<<(NODE_DIM * NCOLS + 255) / 256, 256>>>(W1, b1, gamma, beta, mean, var);
    dim3 ggrid(NCOLS / BN, (M + BM - 1) / BM);
    gemm_kernel<<<ggrid, 256>>>(node_feat, M);
    edge_kernel<<<(E + 7) / 8, 256>>>(eidx, W2, b2, out, E);
}

// round 3
// speedup vs baseline: 1.3482x; 1.3482x over previous
#include <cuda_runtime.h>
#include <cuda_bf16.h>
#include <cstdint>

#define N_NODES_MAX 50000
#define NODE_DIM    128
#define HIDDEN      256
#define NCOLS       1024   // 4 segments of 256

// ---- scratch (static device globals; no runtime allocation) ----
__device__ float         g_table[(size_t)N_NODES_MAX * NCOLS];   // ~204.8 MB
__device__ __nv_bfloat16 g_Xhi[(size_t)N_NODES_MAX * NODE_DIM];  // 12.8 MB
__device__ __nv_bfloat16 g_Xlo[(size_t)N_NODES_MAX * NODE_DIM];  // 12.8 MB
__device__ __nv_bfloat16 g_WThi[NCOLS * NODE_DIM];               // 256 KB  [n][k]
__device__ __nv_bfloat16 g_WTlo[NCOLS * NODE_DIM];               // 256 KB
__device__ float         g_c[HIDDEN];
__device__ int           g_is64;

__device__ __forceinline__ uint32_t smem_u32(const void* p) {
    uint32_t a;
    asm("{ .reg .u64 t; cvta.to.shared.u64 t, %1; cvt.u32.u64 %0, t; }" : "=r"(a) : "l"(p));
    return a;
}
__device__ __forceinline__ void ldsm_x4(uint32_t& r0, uint32_t& r1, uint32_t& r2, uint32_t& r3,
                                        uint32_t addr) {
    asm volatile("ldmatrix.sync.aligned.m8n8.x4.shared.b16 {%0,%1,%2,%3}, [%4];"
                 : "=r"(r0), "=r"(r1), "=r"(r2), "=r"(r3) : "r"(addr));
}
__device__ __forceinline__ void mma16816(float* c, const uint32_t* a, uint32_t b0, uint32_t b1) {
    asm volatile("mma.sync.aligned.m16n8k16.row.col.f32.bf16.bf16.f32 "
                 "{%0,%1,%2,%3}, {%4,%5,%6,%7}, {%8,%9}, {%0,%1,%2,%3};"
                 : "+f"(c[0]), "+f"(c[1]), "+f"(c[2]), "+f"(c[3])
                 : "r"(a[0]), "r"(a[1]), "r"(a[2]), "r"(a[3]), "r"(b0), "r"(b1));
}

// ---------------------------------------------------------------------------
// int64/int32 edge_index detection (deterministic)
// ---------------------------------------------------------------------------
__global__ void detect_kernel(const int* __restrict__ idx32) {
    int lane = threadIdx.x;
    int acc = 0;
    for (int i = lane; i < 1024; i += 32) acc |= idx32[2 * i + 1];
    #pragma unroll
    for (int s = 16; s; s >>= 1) acc |= __shfl_xor_sync(0xFFFFFFFFu, acc, s);
    if (lane == 0) g_is64 = (acc == 0) ? 1 : 0;
}

// ---------------------------------------------------------------------------
// prep: folded transposed weights (bf16 hi/lo) + bias constant
//   WT[n][k], n = seg*256+h:
//     seg0: W1[k][h]*s    seg1: W1[128+k][h]*s
//     seg2: W1[k+16][h]*s seg3: W1[(k+144)%256][h]*s
// ---------------------------------------------------------------------------
__global__ void prep_w_kernel(const float* __restrict__ W1, const float* __restrict__ b1,
                              const float* __restrict__ gamma, const float* __restrict__ beta,
                              const float* __restrict__ mean, const float* __restrict__ var) {
    int i = blockIdx.x * blockDim.x + threadIdx.x;
    if (i < NCOLS * NODE_DIM) {
        int n = i >> 7;
        int k = i & 127;
        int h = n & 255;
        int seg = n >> 8;
        int srcRow;
        if (seg == 0)      srcRow = k;
        else if (seg == 1) srcRow = 128 + k;
        else if (seg == 2) srcRow = k + 16;
        else               srcRow = (k + 144) & 255;
        float s = gamma[h] * rsqrtf(var[h] + 1e-5f);
        float w = W1[srcRow * 256 + h] * s;
        __nv_bfloat16 hi = __float2bfloat16(w);
        __nv_bfloat16 lo = __float2bfloat16(w - __bfloat162float(hi));
        g_WThi[i] = hi;
        g_WTlo[i] = lo;
    }
    if (i < HIDDEN) {
        float s = gamma[i] * rsqrtf(var[i] + 1e-5f);
        g_c[i] = b1[i] * s + beta[i] - mean[i] * s;
    }
}

__global__ void prep_x_kernel(const float* __restrict__ X, int total) {
    int i = blockIdx.x * blockDim.x + threadIdx.x;
    if (i >= total) return;
    float x = X[i];
    __nv_bfloat16 hi = __float2bfloat16(x);
    __nv_bfloat16 lo = __float2bfloat16(x - __bfloat162float(hi));
    g_Xhi[i] = hi;
    g_Xlo[i] = lo;
}

// ---------------------------------------------------------------------------
// Warp-MMA bf16 GEMM: g_table[M x 1024] = X[M x 128] @ WT^T
// Block 128(M) x 64(N) x 128(K single-shot); 8 warps, each 32x32.
// fp32 ~= Ah*Bh + Ah*Bl + Al*Bh accumulated in fp32 C frags.
// SMEM swizzle: 16B chunk c at row r lives at chunk (c ^ (r&7)).
// ---------------------------------------------------------------------------
#define BM 128
#define BN 64
#define SA_HI 0
#define SA_LO 32768
#define SB_HI 65536
#define SB_LO 81920
#define SM_TOTAL 98304

__global__ __launch_bounds__(256, 2) void gemm_mma_kernel(int M) {
    extern __shared__ char smem[];
    uint32_t sb = smem_u32(smem);
    int tid = threadIdx.x;
    int lane = tid & 31;
    int wid = tid >> 5;
    int wm = wid & 3;     // warp M index (4)
    int wn = wid >> 2;    // warp N index (2)
    int bn = blockIdx.x * BN;
    int bm = blockIdx.y * BM;

    // ---- global -> smem (swizzled), A: 128x128 bf16 hi+lo, B: 64x128 hi+lo
    const uint4* Xhi4 = (const uint4*)g_Xhi;
    const uint4* Xlo4 = (const uint4*)g_Xlo;
    for (int s = tid; s < 2048; s += 256) {
        int row = s >> 4;
        int c   = s & 15;
        int gr = bm + row;
        uint4 vh = make_uint4(0, 0, 0, 0), vl = make_uint4(0, 0, 0, 0);
        if (gr < M) {
            vh = Xhi4[(size_t)gr * 16 + c];
            vl = Xlo4[(size_t)gr * 16 + c];
        }
        uint32_t off = (uint32_t)(row * 256 + ((c ^ (row & 7)) << 4));
        *(uint4*)(smem + SA_HI + off) = vh;
        *(uint4*)(smem + SA_LO + off) = vl;
    }
    const uint4* Whi4 = (const uint4*)g_WThi;
    const uint4* Wlo4 = (const uint4*)g_WTlo;
    for (int s = tid; s < 1024; s += 256) {
        int row = s >> 4;
        int c   = s & 15;
        int gn = bn + row;
        uint4 vh = Whi4[(size_t)gn * 16 + c];
        uint4 vl = Wlo4[(size_t)gn * 16 + c];
        uint32_t off = (uint32_t)(row * 256 + ((c ^ (row & 7)) << 4));
        *(uint4*)(smem + SB_HI + off) = vh;
        *(uint4*)(smem + SB_LO + off) = vl;
    }
    __syncthreads();

    float acc[2][4][4];
    #pragma unroll
    for (int mt = 0; mt < 2; mt++)
        #pragma unroll
        for (int nt = 0; nt < 4; nt++)
            #pragma unroll
            for (int q = 0; q < 4; q++) acc[mt][nt][q] = 0.f;

    // per-thread ldmatrix row/chunk components
    int aR = (lane & 15);
    int aC = lane >> 4;                        // 0/1 -> k-half
    int bR = (lane & 7) + ((lane >> 4) << 3);  // lanes 16-31 -> odd n-tile rows
    int bC = (lane >> 3) & 1;                  // k-half for even n-tile

    const int aSel[3] = {SA_HI, SA_HI, SA_LO};
    const int bSel[3] = {SB_HI, SB_LO, SB_HI};

    #pragma unroll
    for (int p = 0; p < 3; p++) {
        uint32_t aBase = sb + aSel[p];
        uint32_t bBase = sb + bSel[p];
        #pragma unroll
        for (int ks = 0; ks < 8; ks++) {
            uint32_t a[2][4], b[2][4];
            #pragma unroll
            for (int mt = 0; mt < 2; mt++) {
                int row = wm * 32 + mt * 16 + aR;
                int ch  = ks * 2 + aC;
                uint32_t addr = aBase + row * 256 + ((ch ^ (row & 7)) << 4);
                ldsm_x4(a[mt][0], a[mt][1], a[mt][2], a[mt][3], addr);
            }
            #pragma unroll
            for (int np = 0; np < 2; np++) {
                int row = wn * 32 + np * 16 + bR;
                int ch  = ks * 2 + bC;
                uint32_t addr = bBase + row * 256 + ((ch ^ (row & 7)) << 4);
                ldsm_x4(b[np][0], b[np][1], b[np][2], b[np][3], addr);
            }
            #pragma unroll
            for (int mt = 0; mt < 2; mt++)
                #pragma unroll
                for (int nt = 0; nt < 4; nt++)
                    mma16816(acc[mt][nt], a[mt],
                             b[nt >> 1][(nt & 1) * 2], b[nt >> 1][(nt & 1) * 2 + 1]);
        }
    }

    // ---- writeback: C frag: (c0,c1)=row t/4, cols 2(t%4)+{0,1}; (c2,c3)=row+8
    #pragma unroll
    for (int mt = 0; mt < 2; mt++) {
        #pragma unroll
        for (int h = 0; h < 2; h++) {
            int row = bm + wm * 32 + mt * 16 + (lane >> 2) + h * 8;
            if (row < M) {
                float* dst = g_table + (size_t)row * NCOLS + bn + wn * 32 + (lane & 3) * 2;
                #pragma unroll
                for (int nt = 0; nt < 4; nt++) {
                    float2 v = make_float2(acc[mt][nt][h * 2], acc[mt][nt][h * 2 + 1]);
                    *(float2*)(dst + nt * 8) = v;
                }
            }
        }
    }
}

// ---------------------------------------------------------------------------
// Edge kernel: warp per edge (at DRAM roofline)
// ---------------------------------------------------------------------------
__global__ __launch_bounds__(256) void edge_kernel(const void* __restrict__ idx,
                                                   const float* __restrict__ W2,
                                                   const float* __restrict__ b2,
                                                   float* __restrict__ out, int E) {
    int e = blockIdx.x * 8 + (threadIdx.x >> 5);
    if (e >= E) return;
    int lane = threadIdx.x & 31;

    int row, col;
    if (g_is64) {
        const long long* p = (const long long*)idx;
        row = (int)p[e];
        col = (int)p[E + e];
    } else {
        const int* p = (const int*)idx;
        row = p[e];
        col = p[E + e];
    }

    const float* Tr = g_table + (size_t)row * NCOLS;
    const float* Tc = g_table + (size_t)col * NCOLS;

    float acc = 0.f;
    #pragma unroll
    for (int part = 0; part < 2; part++) {
        int off = part * 128 + lane * 4;
        float4 a1  = *(const float4*)(Tr + off);
        float4 b1v = *(const float4*)(Tc + 256 + off);
        float4 a2  = *(const float4*)(Tr + 512 + off);
        float4 b2v = *(const float4*)(Tc + 768 + off);
        float4 cc  = *(const float4*)(g_c + off);
        float4 w   = *(const float4*)(W2 + off);
        acc += fmaxf(a1.x + b1v.x + cc.x, 0.f) * w.x;
        acc += fmaxf(a1.y + b1v.y + cc.y, 0.f) * w.y;
        acc += fmaxf(a1.z + b1v.z + cc.z, 0.f) * w.z;
        acc += fmaxf(a1.w + b1v.w + cc.w, 0.f) * w.w;
        acc += fmaxf(a2.x + b2v.x + cc.x, 0.f) * w.x;
        acc += fmaxf(a2.y + b2v.y + cc.y, 0.f) * w.y;
        acc += fmaxf(a2.z + b2v.z + cc.z, 0.f) * w.z;
        acc += fmaxf(a2.w + b2v.w + cc.w, 0.f) * w.w;
    }
    #pragma unroll
    for (int s = 16; s; s >>= 1) acc += __shfl_xor_sync(0xFFFFFFFFu, acc, s);

    if (lane == 0) {
        float x = acc * 0.5f + b2[0];
        out[e] = 1.f / (1.f + expf(-x));
    }
}

// ---------------------------------------------------------------------------
extern "C" void kernel_launch(void* const* d_in, const int* in_sizes, int n_in,
                              void* d_out, int out_size) {
    const float* node_feat = (const float*)d_in[0];
    const void*  eidx      = d_in[1];
    const float* W1        = (const float*)d_in[2];
    const float* b1        = (const float*)d_in[3];
    const float* gamma     = (const float*)d_in[4];
    const float* beta      = (const float*)d_in[5];
    const float* mean      = (const float*)d_in[6];
    const float* var       = (const float*)d_in[7];
    const float* W2        = (const float*)d_in[8];
    const float* b2        = (const float*)d_in[9];
    float* out = (float*)d_out;

    int M = in_sizes[0] / NODE_DIM;   // 50000
    int E = out_size;                 // 300000

    cudaFuncSetAttribute(gemm_mma_kernel, cudaFuncAttributeMaxDynamicSharedMemorySize, SM_TOTAL);

    detect_kernel<<<1, 32>>>((const int*)eidx);
    prep_w_kernel<<<(NCOLS * NODE_DIM + 255) / 256, 256>>>(W1, b1, gamma, beta, mean, var);
    prep_x_kernel<<<(M * NODE_DIM + 255) / 256, 256>>>(node_feat, M * NODE_DIM);

    dim3 ggrid(NCOLS / BN, (M + BM - 1) / BM);   // (16, 391)
    gemm_mma_kernel<<<ggrid, 256, SM_TOTAL>>>(M);

    edge_kernel<<<(E + 7) / 8, 256>>>(eidx, W2, b2, out, E);
}

// round 4
// speedup vs baseline: 2.0031x; 1.4857x over previous
#include <cuda_runtime.h>
#include <cuda_bf16.h>
#include <cstdint>

#define N_NODES_MAX 50000
#define NODE_DIM    128
#define HIDDEN      256
#define NCOLS       1024   // 4 segments of 256

// ---- scratch (static device globals; no runtime allocation) ----
__device__ __nv_bfloat16 g_table[(size_t)N_NODES_MAX * NCOLS];   // 102.4 MB
__device__ __nv_bfloat16 g_Xhi[(size_t)N_NODES_MAX * NODE_DIM];  // 12.8 MB
__device__ __nv_bfloat16 g_Xlo[(size_t)N_NODES_MAX * NODE_DIM];  // 12.8 MB
__device__ __nv_bfloat16 g_WThi[NCOLS * NODE_DIM];               // 256 KB  [n][k]
__device__ __nv_bfloat16 g_WTlo[NCOLS * NODE_DIM];               // 256 KB
__device__ float         g_c[HIDDEN];
__device__ int           g_is64;

__device__ __forceinline__ uint32_t smem_u32(const void* p) {
    uint32_t a;
    asm("{ .reg .u64 t; cvta.to.shared.u64 t, %1; cvt.u32.u64 %0, t; }" : "=r"(a) : "l"(p));
    return a;
}
__device__ __forceinline__ void ldsm_x4(uint32_t& r0, uint32_t& r1, uint32_t& r2, uint32_t& r3,
                                        uint32_t addr) {
    asm volatile("ldmatrix.sync.aligned.m8n8.x4.shared.b16 {%0,%1,%2,%3}, [%4];"
                 : "=r"(r0), "=r"(r1), "=r"(r2), "=r"(r3) : "r"(addr));
}
__device__ __forceinline__ void mma16816(float* c, const uint32_t* a, uint32_t b0, uint32_t b1) {
    asm volatile("mma.sync.aligned.m16n8k16.row.col.f32.bf16.bf16.f32 "
                 "{%0,%1,%2,%3}, {%4,%5,%6,%7}, {%8,%9}, {%0,%1,%2,%3};"
                 : "+f"(c[0]), "+f"(c[1]), "+f"(c[2]), "+f"(c[3])
                 : "r"(a[0]), "r"(a[1]), "r"(a[2]), "r"(a[3]), "r"(b0), "r"(b1));
}
#define CP16(dst, src) \
    asm volatile("cp.async.cg.shared.global [%0], [%1], 16;" :: "r"(dst), "l"(src))
#define CP16P(dst, src, p) \
    asm volatile("{ .reg .pred q; setp.ne.b32 q, %2, 0;\n\t" \
                 "@q cp.async.cg.shared.global [%0], [%1], 16; }" \
                 :: "r"(dst), "l"(src), "r"(p))
#define CP_COMMIT  asm volatile("cp.async.commit_group;")
#define CP_WAIT1   asm volatile("cp.async.wait_group 1;")

// ---------------------------------------------------------------------------
// int64/int32 edge_index detection (deterministic)
// ---------------------------------------------------------------------------
__global__ void detect_kernel(const int* __restrict__ idx32) {
    int lane = threadIdx.x;
    int acc = 0;
    for (int i = lane; i < 1024; i += 32) acc |= idx32[2 * i + 1];
    #pragma unroll
    for (int s = 16; s; s >>= 1) acc |= __shfl_xor_sync(0xFFFFFFFFu, acc, s);
    if (lane == 0) g_is64 = (acc == 0) ? 1 : 0;
}

// ---------------------------------------------------------------------------
// prep: folded transposed weights (bf16 hi/lo) + bias constant
// ---------------------------------------------------------------------------
__global__ void prep_w_kernel(const float* __restrict__ W1, const float* __restrict__ b1,
                              const float* __restrict__ gamma, const float* __restrict__ beta,
                              const float* __restrict__ mean, const float* __restrict__ var) {
    int i = blockIdx.x * blockDim.x + threadIdx.x;
    if (i < NCOLS * NODE_DIM) {
        int n = i >> 7;
        int k = i & 127;
        int h = n & 255;
        int seg = n >> 8;
        int srcRow;
        if (seg == 0)      srcRow = k;
        else if (seg == 1) srcRow = 128 + k;
        else if (seg == 2) srcRow = k + 16;
        else               srcRow = (k + 144) & 255;
        float s = gamma[h] * rsqrtf(var[h] + 1e-5f);
        float w = W1[srcRow * 256 + h] * s;
        __nv_bfloat16 hi = __float2bfloat16(w);
        __nv_bfloat16 lo = __float2bfloat16(w - __bfloat162float(hi));
        g_WThi[i] = hi;
        g_WTlo[i] = lo;
    }
    if (i < HIDDEN) {
        float s = gamma[i] * rsqrtf(var[i] + 1e-5f);
        g_c[i] = b1[i] * s + beta[i] - mean[i] * s;
    }
}

__global__ void prep_x_kernel(const float* __restrict__ X, int total) {
    int i = blockIdx.x * blockDim.x + threadIdx.x;
    if (i >= total) return;
    float x = X[i];
    __nv_bfloat16 hi = __float2bfloat16(x);
    __nv_bfloat16 lo = __float2bfloat16(x - __bfloat162float(hi));
    g_Xhi[i] = hi;
    g_Xlo[i] = lo;
}

// ---------------------------------------------------------------------------
// Persistent pipelined warp-MMA bf16 GEMM: table[M x 1024] = X[M x 128] @ WT^T
// Grid (16, NY): CTA owns one bn (64 cols), sweeps bm tiles (stride NY),
// cp.async double-buffered A stages; B resident. 8 warps, 32x32 each.
// 3 precision passes (Ah*Bh + Ah*Bl + Al*Bh) from hoisted register frags.
// ---------------------------------------------------------------------------
#define BM 128
#define BN 64
#define SM_B_HI 0
#define SM_B_LO 16384
#define SM_A    32768
#define A_STAGE 65536       // per stage: hi 32KB + lo 32KB
#define SM_TOTAL (32768 + 2 * 65536)   // 160 KB

__global__ __launch_bounds__(256, 1) void gemm_mma_kernel(int M) {
    extern __shared__ char smem[];
    uint32_t sb = smem_u32(smem);
    int tid = threadIdx.x;
    int lane = tid & 31;
    int wid = tid >> 5;
    int wm = wid & 3;
    int wn = wid >> 2;
    int bn = blockIdx.x * BN;
    int y = blockIdx.y;
    int NY = gridDim.y;
    int totTiles = (M + BM - 1) / BM;

    // ---- B tile (64 n-rows x 128 k), hi+lo, swizzled, via cp.async (group 0)
    for (int s = tid; s < 1024; s += 256) {
        int row = s >> 4;
        int c = s & 15;
        uint32_t off = (uint32_t)(row * 256 + ((c ^ (row & 7)) << 4));
        CP16(sb + SM_B_HI + off, (const char*)(g_WThi + (size_t)(bn + row) * 128 + c * 8));
        CP16(sb + SM_B_LO + off, (const char*)(g_WTlo + (size_t)(bn + row) * 128 + c * 8));
    }
    CP_COMMIT;

    // ---- A prefetch helper
    auto prefetchA = [&](int t, int st) {
        int bm = t * BM;
        uint32_t base = sb + SM_A + st * A_STAGE;
        for (int s = tid; s < 2048; s += 256) {
            int row = s >> 4;
            int c = s & 15;
            int gr = bm + row;
            int valid = (gr < M) ? 1 : 0;
            uint32_t off = (uint32_t)(row * 256 + ((c ^ (row & 7)) << 4));
            CP16P(base + off,         (const char*)(g_Xhi + (size_t)gr * 128 + c * 8), valid);
            CP16P(base + 32768 + off, (const char*)(g_Xlo + (size_t)gr * 128 + c * 8), valid);
        }
        CP_COMMIT;
    };

    if (y < totTiles) prefetchA(y, 0); else CP_COMMIT;

    // per-thread ldmatrix row/chunk components
    int aR = (lane & 15);
    int aC = lane >> 4;
    int bR = (lane & 7) + ((lane >> 4) << 3);
    int bC = (lane >> 3) & 1;

    int i = 0;
    for (int t = y; t < totTiles; t += NY, i++) {
        int tn = t + NY;
        if (tn < totTiles) prefetchA(tn, (i + 1) & 1); else CP_COMMIT;
        CP_WAIT1;
        __syncthreads();

        uint32_t aBase = sb + SM_A + (i & 1) * A_STAGE;

        float acc[2][4][4];
        #pragma unroll
        for (int mt = 0; mt < 2; mt++)
            #pragma unroll
            for (int nt = 0; nt < 4; nt++)
                #pragma unroll
                for (int q = 0; q < 4; q++) acc[mt][nt][q] = 0.f;

        #pragma unroll
        for (int ks = 0; ks < 8; ks++) {
            uint32_t ah[2][4], al[2][4], bh[2][4], bl[2][4];
            #pragma unroll
            for (int mt = 0; mt < 2; mt++) {
                int row = wm * 32 + mt * 16 + aR;
                int ch = ks * 2 + aC;
                uint32_t off = (uint32_t)(row * 256 + ((ch ^ (row & 7)) << 4));
                ldsm_x4(ah[mt][0], ah[mt][1], ah[mt][2], ah[mt][3], aBase + off);
                ldsm_x4(al[mt][0], al[mt][1], al[mt][2], al[mt][3], aBase + 32768 + off);
            }
            #pragma unroll
            for (int np = 0; np < 2; np++) {
                int row = wn * 32 + np * 16 + bR;
                int ch = ks * 2 + bC;
                uint32_t off = (uint32_t)(row * 256 + ((ch ^ (row & 7)) << 4));
                ldsm_x4(bh[np][0], bh[np][1], bh[np][2], bh[np][3], sb + SM_B_HI + off);
                ldsm_x4(bl[np][0], bl[np][1], bl[np][2], bl[np][3], sb + SM_B_LO + off);
            }
            #pragma unroll
            for (int mt = 0; mt < 2; mt++)
                #pragma unroll
                for (int nt = 0; nt < 4; nt++) {
                    int hp = nt >> 1, qp = (nt & 1) * 2;
                    mma16816(acc[mt][nt], ah[mt], bh[hp][qp], bh[hp][qp + 1]);
                    mma16816(acc[mt][nt], ah[mt], bl[hp][qp], bl[hp][qp + 1]);
                    mma16816(acc[mt][nt], al[mt], bh[hp][qp], bh[hp][qp + 1]);
                }
        }

        // writeback bf16
        int bm = t * BM;
        #pragma unroll
        for (int mt = 0; mt < 2; mt++) {
            #pragma unroll
            for (int h = 0; h < 2; h++) {
                int row = bm + wm * 32 + mt * 16 + (lane >> 2) + h * 8;
                if (row < M) {
                    __nv_bfloat16* dst = g_table + (size_t)row * NCOLS + bn + wn * 32 + (lane & 3) * 2;
                    #pragma unroll
                    for (int nt = 0; nt < 4; nt++)
                        *(__nv_bfloat162*)(dst + nt * 8) =
                            __floats2bfloat162_rn(acc[mt][nt][h * 2], acc[mt][nt][h * 2 + 1]);
                }
            }
        }
        __syncthreads();
    }
}

// ---------------------------------------------------------------------------
// Edge kernel: warp per edge; bf16 table, single 16B gather per stream.
// ---------------------------------------------------------------------------
__global__ __launch_bounds__(256) void edge_kernel(const void* __restrict__ idx,
                                                   const float* __restrict__ W2,
                                                   const float* __restrict__ b2,
                                                   float* __restrict__ out, int E) {
    int e = blockIdx.x * 8 + (threadIdx.x >> 5);
    if (e >= E) return;
    int lane = threadIdx.x & 31;

    int row, col;
    if (g_is64) {
        const long long* p = (const long long*)idx;
        row = (int)p[e];
        col = (int)p[E + e];
    } else {
        const int* p = (const int*)idx;
        row = p[e];
        col = p[E + e];
    }

    const __nv_bfloat16* Tr = g_table + (size_t)row * NCOLS;
    const __nv_bfloat16* Tc = g_table + (size_t)col * NCOLS;
    int o = lane * 8;

    uint4 x1 = *(const uint4*)(Tr + o);
    uint4 y1 = *(const uint4*)(Tc + 256 + o);
    uint4 x2 = *(const uint4*)(Tr + 512 + o);
    uint4 y2 = *(const uint4*)(Tc + 768 + o);

    const uint32_t* px1 = &x1.x;
    const uint32_t* py1 = &y1.x;
    const uint32_t* px2 = &x2.x;
    const uint32_t* py2 = &y2.x;

    float acc = 0.f;
    #pragma unroll
    for (int j = 0; j < 4; j++) {
        float2 fa1 = __bfloat1622float2(*reinterpret_cast<const __nv_bfloat162*>(&px1[j]));
        float2 fb1 = __bfloat1622float2(*reinterpret_cast<const __nv_bfloat162*>(&py1[j]));
        float2 fa2 = __bfloat1622float2(*reinterpret_cast<const __nv_bfloat162*>(&px2[j]));
        float2 fb2 = __bfloat1622float2(*reinterpret_cast<const __nv_bfloat162*>(&py2[j]));
        float2 cc = *(const float2*)(g_c + o + j * 2);
        float2 ww = *(const float2*)(W2 + o + j * 2);
        acc += fmaxf(fa1.x + fb1.x + cc.x, 0.f) * ww.x;
        acc += fmaxf(fa1.y + fb1.y + cc.y, 0.f) * ww.y;
        acc += fmaxf(fa2.x + fb2.x + cc.x, 0.f) * ww.x;
        acc += fmaxf(fa2.y + fb2.y + cc.y, 0.f) * ww.y;
    }
    #pragma unroll
    for (int s = 16; s; s >>= 1) acc += __shfl_xor_sync(0xFFFFFFFFu, acc, s);

    if (lane == 0) {
        float x = acc * 0.5f + b2[0];
        out[e] = 1.f / (1.f + expf(-x));
    }
}

// ---------------------------------------------------------------------------
extern "C" void kernel_launch(void* const* d_in, const int* in_sizes, int n_in,
                              void* d_out, int out_size) {
    const float* node_feat = (const float*)d_in[0];
    const void*  eidx      = d_in[1];
    const float* W1        = (const float*)d_in[2];
    const float* b1        = (const float*)d_in[3];
    const float* gamma     = (const float*)d_in[4];
    const float* beta      = (const float*)d_in[5];
    const float* mean      = (const float*)d_in[6];
    const float* var       = (const float*)d_in[7];
    const float* W2        = (const float*)d_in[8];
    const float* b2        = (const float*)d_in[9];
    float* out = (float*)d_out;

    int M = in_sizes[0] / NODE_DIM;   // 50000
    int E = out_size;                 // 300000

    cudaFuncSetAttribute(gemm_mma_kernel, cudaFuncAttributeMaxDynamicSharedMemorySize, SM_TOTAL);

    detect_kernel<<<1, 32>>>((const int*)eidx);
    prep_w_kernel<<<(NCOLS * NODE_DIM + 255) / 256, 256>>>(W1, b1, gamma, beta, mean, var);
    prep_x_kernel<<<(M * NODE_DIM + 255) / 256, 256>>>(node_feat, M * NODE_DIM);

    dim3 ggrid(NCOLS / BN, 9);   // (16, 9) = 144 persistent CTAs
    gemm_mma_kernel<<<ggrid, 256, SM_TOTAL>>>(M);

    edge_kernel<<<(E + 7) / 8, 256>>>(eidx, W2, b2, out, E);
}

// round 5
// speedup vs baseline: 2.4913x; 1.2437x over previous
#include <cuda_runtime.h>
#include <cuda_bf16.h>
#include <cstdint>

#define N_NODES_MAX 50000
#define NODE_DIM    128
#define HIDDEN      256
#define NCOLS       1024

// Table column layout (permuted for edge locality):
//   [0:256)   = seg0 (p1 row-role)
//   [256:512) = seg2 (p2 row-role)
//   [512:768) = seg1 (p1 col-role)
//   [768:1024)= seg3 (p2 col-role)

// ---- scratch (static device globals; no runtime allocation) ----
__device__ __nv_bfloat16 g_table[(size_t)N_NODES_MAX * NCOLS];   // 102.4 MB
__device__ __nv_bfloat16 g_Xhi[(size_t)N_NODES_MAX * NODE_DIM];
__device__ __nv_bfloat16 g_Xlo[(size_t)N_NODES_MAX * NODE_DIM];
__device__ __nv_bfloat16 g_WThi[NCOLS * NODE_DIM];               // [n][k] permuted
__device__ float         g_c[HIDDEN];
__device__ int           g_is64;

__device__ __forceinline__ uint32_t smem_u32(const void* p) {
    uint32_t a;
    asm("{ .reg .u64 t; cvta.to.shared.u64 t, %1; cvt.u32.u64 %0, t; }" : "=r"(a) : "l"(p));
    return a;
}
__device__ __forceinline__ void ldsm_x4(uint32_t& r0, uint32_t& r1, uint32_t& r2, uint32_t& r3,
                                        uint32_t addr) {
    asm volatile("ldmatrix.sync.aligned.m8n8.x4.shared.b16 {%0,%1,%2,%3}, [%4];"
                 : "=r"(r0), "=r"(r1), "=r"(r2), "=r"(r3) : "r"(addr));
}
__device__ __forceinline__ void mma16816(float* c, const uint32_t* a, uint32_t b0, uint32_t b1) {
    asm volatile("mma.sync.aligned.m16n8k16.row.col.f32.bf16.bf16.f32 "
                 "{%0,%1,%2,%3}, {%4,%5,%6,%7}, {%8,%9}, {%0,%1,%2,%3};"
                 : "+f"(c[0]), "+f"(c[1]), "+f"(c[2]), "+f"(c[3])
                 : "r"(a[0]), "r"(a[1]), "r"(a[2]), "r"(a[3]), "r"(b0), "r"(b1));
}
#define CP16(dst, src) \
    asm volatile("cp.async.cg.shared.global [%0], [%1], 16;" :: "r"(dst), "l"(src))
#define CP16P(dst, src, p) \
    asm volatile("{ .reg .pred q; setp.ne.b32 q, %2, 0;\n\t" \
                 "@q cp.async.cg.shared.global [%0], [%1], 16; }" \
                 :: "r"(dst), "l"(src), "r"(p))
#define CP_COMMIT  asm volatile("cp.async.commit_group;")
#define CP_WAIT1   asm volatile("cp.async.wait_group 1;")

// ---------------------------------------------------------------------------
__global__ void detect_kernel(const int* __restrict__ idx32) {
    int lane = threadIdx.x;
    int acc = 0;
    for (int i = lane; i < 1024; i += 32) acc |= idx32[2 * i + 1];
    #pragma unroll
    for (int s = 16; s; s >>= 1) acc |= __shfl_xor_sync(0xFFFFFFFFu, acc, s);
    if (lane == 0) g_is64 = (acc == 0) ? 1 : 0;
}

// ---------------------------------------------------------------------------
// prep: folded transposed weights (bf16 hi only) + bias constant, PERMUTED:
//   new grp 0 -> seg0: srcRow=k         new grp 1 -> seg2: srcRow=k+16
//   new grp 2 -> seg1: srcRow=128+k     new grp 3 -> seg3: srcRow=(k+144)&255
// ---------------------------------------------------------------------------
__global__ void prep_w_kernel(const float* __restrict__ W1, const float* __restrict__ b1,
                              const float* __restrict__ gamma, const float* __restrict__ beta,
                              const float* __restrict__ mean, const float* __restrict__ var) {
    int i = blockIdx.x * blockDim.x + threadIdx.x;
    if (i < NCOLS * NODE_DIM) {
        int n = i >> 7;
        int k = i & 127;
        int h = n & 255;
        int grp = n >> 8;
        int srcRow;
        if (grp == 0)      srcRow = k;
        else if (grp == 1) srcRow = k + 16;
        else if (grp == 2) srcRow = 128 + k;
        else               srcRow = (k + 144) & 255;
        float s = gamma[h] * rsqrtf(var[h] + 1e-5f);
        g_WThi[i] = __float2bfloat16(W1[srcRow * 256 + h] * s);
    }
    if (i < HIDDEN) {
        float s = gamma[i] * rsqrtf(var[i] + 1e-5f);
        g_c[i] = b1[i] * s + beta[i] - mean[i] * s;
    }
}

__global__ void prep_x_kernel(const float* __restrict__ X, int total) {
    int i = blockIdx.x * blockDim.x + threadIdx.x;
    if (i >= total) return;
    float x = X[i];
    __nv_bfloat16 hi = __float2bfloat16(x);
    __nv_bfloat16 lo = __float2bfloat16(x - __bfloat162float(hi));
    g_Xhi[i] = hi;
    g_Xlo[i] = lo;
}

// ---------------------------------------------------------------------------
// Persistent pipelined warp-MMA bf16 GEMM, 2 passes: Ah*Bh + Al*Bh
// ---------------------------------------------------------------------------
#define BM 128
#define BN 64
#define SM_B_HI 0
#define SM_A    16384
#define A_STAGE 65536       // hi 32KB + lo 32KB
#define SM_TOTAL (16384 + 2 * 65536)   // 144 KB

__global__ __launch_bounds__(256, 1) void gemm_mma_kernel(int M) {
    extern __shared__ char smem[];
    uint32_t sb = smem_u32(smem);
    int tid = threadIdx.x;
    int lane = tid & 31;
    int wid = tid >> 5;
    int wm = wid & 3;
    int wn = wid >> 2;
    int bn = blockIdx.x * BN;
    int y = blockIdx.y;
    int NY = gridDim.y;
    int totTiles = (M + BM - 1) / BM;

    for (int s = tid; s < 1024; s += 256) {
        int row = s >> 4;
        int c = s & 15;
        uint32_t off = (uint32_t)(row * 256 + ((c ^ (row & 7)) << 4));
        CP16(sb + SM_B_HI + off, (const char*)(g_WThi + (size_t)(bn + row) * 128 + c * 8));
    }
    CP_COMMIT;

    auto prefetchA = [&](int t, int st) {
        int bm = t * BM;
        uint32_t base = sb + SM_A + st * A_STAGE;
        for (int s = tid; s < 2048; s += 256) {
            int row = s >> 4;
            int c = s & 15;
            int gr = bm + row;
            int valid = (gr < M) ? 1 : 0;
            uint32_t off = (uint32_t)(row * 256 + ((c ^ (row & 7)) << 4));
            CP16P(base + off,         (const char*)(g_Xhi + (size_t)gr * 128 + c * 8), valid);
            CP16P(base + 32768 + off, (const char*)(g_Xlo + (size_t)gr * 128 + c * 8), valid);
        }
        CP_COMMIT;
    };

    if (y < totTiles) prefetchA(y, 0); else CP_COMMIT;

    int aR = (lane & 15);
    int aC = lane >> 4;
    int bR = (lane & 7) + ((lane >> 4) << 3);
    int bC = (lane >> 3) & 1;

    int i = 0;
    for (int t = y; t < totTiles; t += NY, i++) {
        int tn = t + NY;
        if (tn < totTiles) prefetchA(tn, (i + 1) & 1); else CP_COMMIT;
        CP_WAIT1;
        __syncthreads();

        uint32_t aBase = sb + SM_A + (i & 1) * A_STAGE;

        float acc[2][4][4];
        #pragma unroll
        for (int mt = 0; mt < 2; mt++)
            #pragma unroll
            for (int nt = 0; nt < 4; nt++)
                #pragma unroll
                for (int q = 0; q < 4; q++) acc[mt][nt][q] = 0.f;

        #pragma unroll
        for (int ks = 0; ks < 8; ks++) {
            uint32_t ah[2][4], al[2][4], bh[2][4];
            #pragma unroll
            for (int mt = 0; mt < 2; mt++) {
                int row = wm * 32 + mt * 16 + aR;
                int ch = ks * 2 + aC;
                uint32_t off = (uint32_t)(row * 256 + ((ch ^ (row & 7)) << 4));
                ldsm_x4(ah[mt][0], ah[mt][1], ah[mt][2], ah[mt][3], aBase + off);
                ldsm_x4(al[mt][0], al[mt][1], al[mt][2], al[mt][3], aBase + 32768 + off);
            }
            #pragma unroll
            for (int np = 0; np < 2; np++) {
                int row = wn * 32 + np * 16 + bR;
                int ch = ks * 2 + bC;
                uint32_t off = (uint32_t)(row * 256 + ((ch ^ (row & 7)) << 4));
                ldsm_x4(bh[np][0], bh[np][1], bh[np][2], bh[np][3], sb + SM_B_HI + off);
            }
            #pragma unroll
            for (int mt = 0; mt < 2; mt++)
                #pragma unroll
                for (int nt = 0; nt < 4; nt++) {
                    int hp = nt >> 1, qp = (nt & 1) * 2;
                    mma16816(acc[mt][nt], ah[mt], bh[hp][qp], bh[hp][qp + 1]);
                    mma16816(acc[mt][nt], al[mt], bh[hp][qp], bh[hp][qp + 1]);
                }
        }

        int bm = t * BM;
        #pragma unroll
        for (int mt = 0; mt < 2; mt++) {
            #pragma unroll
            for (int h = 0; h < 2; h++) {
                int row = bm + wm * 32 + mt * 16 + (lane >> 2) + h * 8;
                if (row < M) {
                    __nv_bfloat16* dst = g_table + (size_t)row * NCOLS + bn + wn * 32 + (lane & 3) * 2;
                    #pragma unroll
                    for (int nt = 0; nt < 4; nt++)
                        *(__nv_bfloat162*)(dst + nt * 8) =
                            __floats2bfloat162_rn(acc[mt][nt][h * 2], acc[mt][nt][h * 2 + 1]);
                }
            }
        }
        __syncthreads();
    }
}

// ---------------------------------------------------------------------------
// Edge kernel: warp handles 2 edges; 2 contiguous 1KB streams per edge.
//   p1: Tr[0:256)(seg0) + Tc[512:768)(seg1)
//   p2: Tr[256:512)(seg2) + Tc[768:1024)(seg3)
// ---------------------------------------------------------------------------
__global__ __launch_bounds__(256) void edge_kernel(const void* __restrict__ idx,
                                                   const float* __restrict__ W2,
                                                   const float* __restrict__ b2,
                                                   float* __restrict__ out, int E) {
    int lane = threadIdx.x & 31;
    int e0 = blockIdx.x * 16 + (threadIdx.x >> 5) * 2;
    if (e0 >= E) return;
    bool has2 = (e0 + 1 < E);
    int o = lane * 8;

    int r0, c0, r1 = 0, c1 = 0;
    if (g_is64) {
        const long long* p = (const long long*)idx;
        r0 = (int)p[e0]; c0 = (int)p[E + e0];
        if (has2) { r1 = (int)p[e0 + 1]; c1 = (int)p[E + e0 + 1]; }
    } else {
        const int* p = (const int*)idx;
        r0 = p[e0]; c0 = p[E + e0];
        if (has2) { r1 = p[e0 + 1]; c1 = p[E + e0 + 1]; }
    }

    const __nv_bfloat16* Tr0 = g_table + (size_t)r0 * NCOLS;
    const __nv_bfloat16* Tc0 = g_table + (size_t)c0 * NCOLS;
    const __nv_bfloat16* Tr1 = g_table + (size_t)(has2 ? r1 : r0) * NCOLS;
    const __nv_bfloat16* Tc1 = g_table + (size_t)(has2 ? c1 : c0) * NCOLS;

    // 8 independent 16B loads
    uint4 a0 = *(const uint4*)(Tr0 + o);          // seg0
    uint4 a2 = *(const uint4*)(Tr0 + 256 + o);    // seg2
    uint4 b1 = *(const uint4*)(Tc0 + 512 + o);    // seg1
    uint4 b3 = *(const uint4*)(Tc0 + 768 + o);    // seg3
    uint4 d0 = *(const uint4*)(Tr1 + o);
    uint4 d2 = *(const uint4*)(Tr1 + 256 + o);
    uint4 e1v = *(const uint4*)(Tc1 + 512 + o);
    uint4 e3 = *(const uint4*)(Tc1 + 768 + o);

    float cc[8], ww[8];
    *(float4*)(cc)     = *(const float4*)(g_c + o);
    *(float4*)(cc + 4) = *(const float4*)(g_c + o + 4);
    *(float4*)(ww)     = *(const float4*)(W2 + o);
    *(float4*)(ww + 4) = *(const float4*)(W2 + o + 4);

    const uint32_t* pa0 = &a0.x; const uint32_t* pa2 = &a2.x;
    const uint32_t* pb1 = &b1.x; const uint32_t* pb3 = &b3.x;
    const uint32_t* pd0 = &d0.x; const uint32_t* pd2 = &d2.x;
    const uint32_t* pe1 = &e1v.x; const uint32_t* pe3 = &e3.x;

    float accA = 0.f, accB = 0.f;
    #pragma unroll
    for (int j = 0; j < 4; j++) {
        float2 fa0 = __bfloat1622float2(*reinterpret_cast<const __nv_bfloat162*>(&pa0[j]));
        float2 fb1 = __bfloat1622float2(*reinterpret_cast<const __nv_bfloat162*>(&pb1[j]));
        float2 fa2 = __bfloat1622float2(*reinterpret_cast<const __nv_bfloat162*>(&pa2[j]));
        float2 fb3 = __bfloat1622float2(*reinterpret_cast<const __nv_bfloat162*>(&pb3[j]));
        float2 fd0 = __bfloat1622float2(*reinterpret_cast<const __nv_bfloat162*>(&pd0[j]));
        float2 fe1 = __bfloat1622float2(*reinterpret_cast<const __nv_bfloat162*>(&pe1[j]));
        float2 fd2 = __bfloat1622float2(*reinterpret_cast<const __nv_bfloat162*>(&pd2[j]));
        float2 fe3 = __bfloat1622float2(*reinterpret_cast<const __nv_bfloat162*>(&pe3[j]));
        float cx = cc[j * 2], cy = cc[j * 2 + 1];
        float wx = ww[j * 2], wy = ww[j * 2 + 1];
        accA += fmaxf(fa0.x + fb1.x + cx, 0.f) * wx;
        accA += fmaxf(fa0.y + fb1.y + cy, 0.f) * wy;
        accA += fmaxf(fa2.x + fb3.x + cx, 0.f) * wx;
        accA += fmaxf(fa2.y + fb3.y + cy, 0.f) * wy;
        accB += fmaxf(fd0.x + fe1.x + cx, 0.f) * wx;
        accB += fmaxf(fd0.y + fe1.y + cy, 0.f) * wy;
        accB += fmaxf(fd2.x + fe3.x + cx, 0.f) * wx;
        accB += fmaxf(fd2.y + fe3.y + cy, 0.f) * wy;
    }
    #pragma unroll
    for (int s = 16; s; s >>= 1) {
        accA += __shfl_xor_sync(0xFFFFFFFFu, accA, s);
        accB += __shfl_xor_sync(0xFFFFFFFFu, accB, s);
    }

    if (lane == 0) {
        float x = accA * 0.5f + b2[0];
        out[e0] = 1.f / (1.f + expf(-x));
        if (has2) {
            float x2 = accB * 0.5f + b2[0];
            out[e0 + 1] = 1.f / (1.f + expf(-x2));
        }
    }
}

// ---------------------------------------------------------------------------
extern "C" void kernel_launch(void* const* d_in, const int* in_sizes, int n_in,
                              void* d_out, int out_size) {
    const float* node_feat = (const float*)d_in[0];
    const void*  eidx      = d_in[1];
    const float* W1        = (const float*)d_in[2];
    const float* b1        = (const float*)d_in[3];
    const float* gamma     = (const float*)d_in[4];
    const float* beta      = (const float*)d_in[5];
    const float* mean      = (const float*)d_in[6];
    const float* var       = (const float*)d_in[7];
    const float* W2        = (const float*)d_in[8];
    const float* b2        = (const float*)d_in[9];
    float* out = (float*)d_out;

    int M = in_sizes[0] / NODE_DIM;   // 50000
    int E = out_size;                 // 300000

    cudaFuncSetAttribute(gemm_mma_kernel, cudaFuncAttributeMaxDynamicSharedMemorySize, SM_TOTAL);

    detect_kernel<<<1, 32>>>((const int*)eidx);
    prep_w_kernel<<<(NCOLS * NODE_DIM + 255) / 256, 256>>>(W1, b1, gamma, beta, mean, var);
    prep_x_kernel<<<(M * NODE_DIM + 255) / 256, 256>>>(node_feat, M * NODE_DIM);

    dim3 ggrid(NCOLS / BN, 9);   // 144 persistent CTAs
    gemm_mma_kernel<<<ggrid, 256, SM_TOTAL>>>(M);

    edge_kernel<<<(E + 15) / 16, 256>>>(eidx, W2, b2, out, E);
}